// round 16
// baseline (speedup 1.0000x reference)
#include <cuda_runtime.h>
#include <cuda_fp16.h>
#include <mma.h>
#include <stdint.h>

#define IN_F   256
#define OUT_F  64
#define MAX_NODES 100000
#define MAX_EDGES 1600000
#define SLOT_E   32     // edges per 16-lane slot
#define BLK_E    256    // edges per 128-thread gather block

// ---------------------------------------------------------------------------
// Device-global scratch (allocation-free)
// ---------------------------------------------------------------------------
__device__ __half g_h0[(size_t)MAX_NODES * OUT_F];   // gemm output
__device__ __half g_h1[(size_t)MAX_NODES * OUT_F];   // hop1 target (pre-zeroed)
__device__ __half g_h2[(size_t)MAX_NODES * OUT_F];   // hop2 target (pre-zeroed)
__device__ int   g_deg[MAX_NODES];
__device__ int   g_off[MAX_NODES];    // partial (per-1024-block) offsets
__device__ int   g_off2[MAX_NODES];   // finalized offsets (scanC output)
__device__ int   g_rank[MAX_EDGES];
__device__ int   g_bsum[128];
__device__ int4  g_csr[MAX_EDGES];    // (src, wbits, dst, 0), sorted by dst

// ---------------------------------------------------------------------------
// Tensor-core GEMM: y[n,f] = fp16( x@W.T + b )
// ---------------------------------------------------------------------------
#define GM 128
#define ALD 24

union GemmSmem {
    struct {
        __half Ws[OUT_F * IN_F];   // 32768 B
        __half As[GM * ALD];       //  6144 B
    } in;
    float stage[GM * OUT_F];       // 32768 B
};

__global__ __launch_bounds__(256) void sgc_gemm_kernel(
    const float* __restrict__ x, const float* __restrict__ W,
    const float* __restrict__ bias, __half* __restrict__ y, int n_nodes)
{
    using namespace nvcuda;
    __shared__ GemmSmem sm;

    const int t    = threadIdx.x;
    const int warp = t >> 5;
    const int node_base = blockIdx.x * GM;

    {   // Stage W (fp32) -> fp16 smem
        const float4* src = reinterpret_cast<const float4*>(W);
        __half2* dst = reinterpret_cast<__half2*>(sm.in.Ws);
        #pragma unroll
        for (int r = 0; r < 16; r++) {
            int idx4 = t + r * 256;
            float4 v = src[idx4];
            dst[idx4 * 2 + 0] = __floats2half2_rn(v.x, v.y);
            dst[idx4 * 2 + 1] = __floats2half2_rn(v.z, v.w);
        }
    }

    wmma::fragment<wmma::accumulator, 16, 16, 16, float> c[4];
    #pragma unroll
    for (int j = 0; j < 4; j++) wmma::fill_fragment(c[j], 0.0f);

    for (int k0 = 0; k0 < IN_F; k0 += 16) {
        __syncthreads();
        #pragma unroll
        for (int r = 0; r < 2; r++) {
            int idx = t + r * 256;
            int row = idx >> 2;
            int q   = idx & 3;
            int gn  = node_base + row;
            float4 v = make_float4(0.f, 0.f, 0.f, 0.f);
            if (gn < n_nodes)
                v = *reinterpret_cast<const float4*>(x + (size_t)gn * IN_F + k0 + q * 4);
            __half2* p = reinterpret_cast<__half2*>(&sm.in.As[row * ALD + q * 4]);
            p[0] = __floats2half2_rn(v.x, v.y);
            p[1] = __floats2half2_rn(v.z, v.w);
        }
        __syncthreads();

        wmma::fragment<wmma::matrix_a, 16, 16, 16, __half, wmma::row_major> a;
        wmma::load_matrix_sync(a, &sm.in.As[warp * 16 * ALD], ALD);
        #pragma unroll
        for (int j = 0; j < 4; j++) {
            wmma::fragment<wmma::matrix_b, 16, 16, 16, __half, wmma::col_major> bf;
            wmma::load_matrix_sync(bf, &sm.in.Ws[(j * 16) * IN_F + k0], IN_F);
            wmma::mma_sync(c[j], a, bf, c[j]);
        }
    }

    __syncthreads();
    #pragma unroll
    for (int j = 0; j < 4; j++)
        wmma::store_matrix_sync(&sm.stage[(warp * 16) * OUT_F + j * 16], c[j],
                                OUT_F, wmma::mem_row_major);
    __syncthreads();

    {
        int row  = t >> 1;
        int part = (t & 1) * 32;
        int gn   = node_base + row;
        if (gn < n_nodes) {
            uint4 o[1];
            __half* oh = reinterpret_cast<__half*>(o);
            #pragma unroll
            for (int seg = 0; seg < 4; seg++) {
                #pragma unroll
                for (int cix = 0; cix < 8; cix++) {
                    int f = part + seg * 8 + cix;
                    oh[cix] = __float2half(sm.stage[row * OUT_F + f] + bias[f]);
                }
                reinterpret_cast<uint4*>(y + (size_t)gn * OUT_F + part)[seg] = o[0];
            }
        }
    }
}

// ---------------------------------------------------------------------------
// CSR build
// ---------------------------------------------------------------------------
__global__ void sgc_hist(const int* __restrict__ dst, int* __restrict__ deg,
                         int* __restrict__ rank, int E)
{
    int i = blockIdx.x * blockDim.x + threadIdx.x;
    if (i < E) rank[i] = atomicAdd(&deg[dst[i]], 1);
}

__global__ void sgc_scanA(const int* __restrict__ deg, int* __restrict__ off,
                          int* __restrict__ bsum, int n)
{
    __shared__ int s[256];
    int t = threadIdx.x;
    int base = blockIdx.x * 1024 + t * 4;
    int v0 = (base + 0 < n) ? deg[base + 0] : 0;
    int v1 = (base + 1 < n) ? deg[base + 1] : 0;
    int v2 = (base + 2 < n) ? deg[base + 2] : 0;
    int v3 = (base + 3 < n) ? deg[base + 3] : 0;
    int tsum = v0 + v1 + v2 + v3;
    s[t] = tsum;
    __syncthreads();
    for (int o = 1; o < 256; o <<= 1) {
        int xv = (t >= o) ? s[t - o] : 0;
        __syncthreads();
        s[t] += xv;
        __syncthreads();
    }
    int excl = s[t] - tsum;
    if (t == 255) bsum[blockIdx.x] = s[255];
    if (base + 0 < n) off[base + 0] = excl;
    if (base + 1 < n) off[base + 1] = excl + v0;
    if (base + 2 < n) off[base + 2] = excl + v0 + v1;
    if (base + 3 < n) off[base + 3] = excl + v0 + v1 + v2;
}

__global__ void sgc_scanC(const int* __restrict__ off, int* __restrict__ off2,
                          const int* __restrict__ bsum, int n, int nb)
{
    __shared__ int s[128];
    int t = threadIdx.x;
    if (t < 128) s[t] = (t < nb) ? bsum[t] : 0;
    __syncthreads();
    #pragma unroll
    for (int o = 1; o < 128; o <<= 1) {
        int v = (t < 128 && t >= o) ? s[t - o] : 0;
        __syncthreads();
        if (t < 128) s[t] += v;
        __syncthreads();
    }
    int i = blockIdx.x * 256 + t;
    if (i < n) {
        int blk = i >> 10;
        int pref = (blk == 0) ? 0 : s[blk - 1];
        off2[i] = off[i] + pref;
    }
}

__global__ void sgc_reorder(const int* __restrict__ src, const int* __restrict__ dst,
                            const float* __restrict__ wt,
                            const int* __restrict__ offp, const int* __restrict__ rank,
                            const int* __restrict__ bsum, int nb,
                            int4* __restrict__ csr, int E, int T)
{
    __shared__ int s[128];
    int t = threadIdx.x;
    if (t < 128) s[t] = (t < nb) ? bsum[t] : 0;
    __syncthreads();
    #pragma unroll
    for (int o = 1; o < 128; o <<= 1) {
        int v = (t < 128 && t >= o) ? s[t - o] : 0;
        __syncthreads();
        if (t < 128) s[t] += v;
        __syncthreads();
    }

    int i0 = blockIdx.x * blockDim.x + t;
    int i1 = i0 + T, i2 = i0 + 2 * T, i3 = i0 + 3 * T;

    int d0 = (i0 < E) ? dst[i0] : 0;
    int d1 = (i1 < E) ? dst[i1] : 0;
    int d2 = (i2 < E) ? dst[i2] : 0;
    int d3 = (i3 < E) ? dst[i3] : 0;
    int r0 = (i0 < E) ? rank[i0] : 0;
    int r1 = (i1 < E) ? rank[i1] : 0;
    int r2 = (i2 < E) ? rank[i2] : 0;
    int r3 = (i3 < E) ? rank[i3] : 0;
    int o0 = __ldg(offp + d0);
    int o1 = __ldg(offp + d1);
    int o2 = __ldg(offp + d2);
    int o3 = __ldg(offp + d3);
    o0 += (d0 >> 10) ? s[(d0 >> 10) - 1] : 0;
    o1 += (d1 >> 10) ? s[(d1 >> 10) - 1] : 0;
    o2 += (d2 >> 10) ? s[(d2 >> 10) - 1] : 0;
    o3 += (d3 >> 10) ? s[(d3 >> 10) - 1] : 0;
    if (i0 < E) csr[o0 + r0] = make_int4(src[i0], __float_as_int(wt[i0]), d0, 0);
    if (i1 < E) csr[o1 + r1] = make_int4(src[i1], __float_as_int(wt[i1]), d1, 0);
    if (i2 < E) csr[o2 + r2] = make_int4(src[i2], __float_as_int(wt[i2]), d2, 0);
    if (i3 < E) csr[o3 + r3] = make_int4(src[i3], __float_as_int(wt[i3]), d3, 0);
}

// ---------------------------------------------------------------------------
// Gather hop with cp.async.cg feature staging (LDGSTS path: no outstanding-
// miss cap, unlike LDG's ~55/warp MSHR budget). 128-thread block owns
// BLK_E=256 dst-sorted edges; each lane stages 2 edges' 128B rows via 8x16B
// cp.async into 32KB smem; then 16-lane slots consume with register dst-run
// accumulation (R15-proven flush: plain store interior, atomics at borders).
// ---------------------------------------------------------------------------
__device__ __forceinline__ void flushH(__half* B, int d, int fl, float4 acc,
                                       bool shared)
{
    __half2 h0 = __floats2half2_rn(acc.x, acc.y);
    __half2 h1 = __floats2half2_rn(acc.z, acc.w);
    unsigned u0 = *reinterpret_cast<unsigned*>(&h0);
    unsigned u1 = *reinterpret_cast<unsigned*>(&h1);
    __half* p = B + (size_t)d * OUT_F + fl * 4;
    if (shared) {
        asm volatile("red.global.add.noftz.f16x2 [%0], %1;"
                     :: "l"(p), "r"(u0) : "memory");
        asm volatile("red.global.add.noftz.f16x2 [%0], %1;"
                     :: "l"(p + 2), "r"(u1) : "memory");
    } else {
        *reinterpret_cast<uint2*>(p) = make_uint2(u0, u1);
    }
}

__device__ __forceinline__ void flushF(float* B, int d, int fl, float4 acc,
                                       bool shared)
{
    float* p = B + (size_t)d * OUT_F + fl * 4;
    if (shared) {
        asm volatile("red.global.add.v4.f32 [%0], {%1, %2, %3, %4};"
                     :: "l"(p), "f"(acc.x), "f"(acc.y), "f"(acc.z), "f"(acc.w)
                     : "memory");
    } else {
        *reinterpret_cast<float4*>(p) = acc;
    }
}

template <bool LAST>
__global__ __launch_bounds__(128) void sgc_gather_kernel(
    const __half* __restrict__ A, __half* __restrict__ Bh, float* __restrict__ Bf,
    const int4* __restrict__ csr, int E)
{
    __shared__ __align__(16) uint2 stage[BLK_E][16];   // 256 x 128B = 32KB

    const int t = threadIdx.x;
    const int w = t >> 5;
    const int l = t & 31;
    const int blockBase = blockIdx.x * BLK_E;

    // --- Stage: lane l of warp w issues cp.async for edges (w*64+2l, +1) ---
    #pragma unroll
    for (int i = 0; i < 2; i++) {
        int le = w * 64 + 2 * l + i;
        int ge = blockBase + le;
        if (ge < E) {
            int srcn = __ldg(&csr[ge]).x;
            const char* gp = reinterpret_cast<const char*>(A) + (size_t)srcn * 128;
            uint32_t sp = (uint32_t)__cvta_generic_to_shared(&stage[le][0]);
            #pragma unroll
            for (int p = 0; p < 8; p++) {
                asm volatile("cp.async.cg.shared.global [%0], [%1], 16;"
                             :: "r"(sp + p * 16), "l"(gp + p * 16));
            }
        }
    }
    asm volatile("cp.async.commit_group;" ::: "memory");
    asm volatile("cp.async.wait_group 0;" ::: "memory");
    __syncwarp();

    // --- Process: 16-lane slot owns SLOT_E contiguous edges ---
    int slot = t >> 4;            // 0..7
    int fl   = t & 15;
    int sBeg = blockBase + slot * SLOT_E;
    if (sBeg >= E) return;
    int sEnd = min(sBeg + SLOT_E, E);

    int prevDst = (sBeg > 0) ? __ldg(&csr[sBeg - 1]).z : -1;
    int d = __ldg(&csr[sBeg]).z;
    bool sharedL = (prevDst == d);

    float4 acc = make_float4(0.f, 0.f, 0.f, 0.f);

    for (int e = sBeg; e < sEnd; e++) {
        int4 c = __ldg(&csr[e]);            // 16-lane broadcast, L1-resident
        uint2 f = stage[e - blockBase][fl]; // conflict-free LDS.64
        if (c.z != d) {
            if (LAST) flushF(Bf, d, fl, acc, sharedL);
            else      flushH(Bh, d, fl, acc, sharedL);
            sharedL = false;
            acc = make_float4(0.f, 0.f, 0.f, 0.f);
            d = c.z;
        }
        float wgt = __int_as_float(c.y);
        float2 f0 = __half22float2(*reinterpret_cast<__half2*>(&f.x));
        float2 f1 = __half22float2(*reinterpret_cast<__half2*>(&f.y));
        acc.x += wgt * f0.x; acc.y += wgt * f0.y;
        acc.z += wgt * f1.x; acc.w += wgt * f1.y;
    }

    bool sharedR = (sEnd < E) && (__ldg(&csr[sEnd]).z == d);
    if (LAST) flushF(Bf, d, fl, acc, sharedL || sharedR);
    else      flushH(Bh, d, fl, acc, sharedL || sharedR);
}

// ---------------------------------------------------------------------------
// Launch: s2 = GEMM + scanC; s3 = target-buffer zeroing; main = CSR + hops.
// ---------------------------------------------------------------------------
extern "C" void kernel_launch(void* const* d_in, const int* in_sizes, int n_in,
                              void* d_out, int out_size)
{
    const float* x   = (const float*)d_in[0];
    const float* W   = (const float*)d_in[1];
    const float* b   = (const float*)d_in[2];
    const int*   src = (const int*)  d_in[3];
    const int*   dst = (const int*)  d_in[4];
    const float* wt  = (const float*)d_in[5];

    const int N = in_sizes[0] / IN_F;
    const int E = in_sizes[3];
    float* out  = (float*)d_out;

    __half *h0, *h1, *h2;
    int *deg, *off, *off2, *rank, *bsum;
    int4 *csr;
    cudaGetSymbolAddress((void**)&h0,   g_h0);
    cudaGetSymbolAddress((void**)&h1,   g_h1);
    cudaGetSymbolAddress((void**)&h2,   g_h2);
    cudaGetSymbolAddress((void**)&deg,  g_deg);
    cudaGetSymbolAddress((void**)&off,  g_off);
    cudaGetSymbolAddress((void**)&off2, g_off2);
    cudaGetSymbolAddress((void**)&rank, g_rank);
    cudaGetSymbolAddress((void**)&bsum, g_bsum);
    cudaGetSymbolAddress((void**)&csr,  g_csr);

    static cudaStream_t s2 = nullptr, s3 = nullptr;
    static cudaEvent_t evFork = nullptr, evA = nullptr, evC = nullptr,
                       evZ = nullptr;
    if (s2 == nullptr) {
        cudaStreamCreateWithFlags(&s2, cudaStreamNonBlocking);
        cudaStreamCreateWithFlags(&s3, cudaStreamNonBlocking);
        cudaEventCreateWithFlags(&evFork, cudaEventDisableTiming);
        cudaEventCreateWithFlags(&evA,    cudaEventDisableTiming);
        cudaEventCreateWithFlags(&evC,    cudaEventDisableTiming);
        cudaEventCreateWithFlags(&evZ,    cudaEventDisableTiming);
    }

    const int NB       = (N + 1023) / 1024;
    const int blksN256 = (N + 255) / 256;
    const int blksE256 = (E + 255) / 256;
    const int gemmBlks = (N + GM - 1) / GM;
    const int gatherBlks = (E + BLK_E - 1) / BLK_E;
    const int reoT     = (E + 3) / 4;
    const int reoBlks  = (reoT + 255) / 256;

    // --- Fork: GEMM on s2, target-buffer zeroing on s3 ---
    cudaEventRecord(evFork, 0);
    cudaStreamWaitEvent(s2, evFork, 0);
    sgc_gemm_kernel<<<gemmBlks, 256, 0, s2>>>(x, W, b, h0, N);

    cudaStreamWaitEvent(s3, evFork, 0);
    cudaMemsetAsync(h1,  0, (size_t)N * OUT_F * sizeof(__half), s3);
    cudaMemsetAsync(h2,  0, (size_t)N * OUT_F * sizeof(__half), s3);
    cudaMemsetAsync(out, 0, (size_t)N * OUT_F * sizeof(float),  s3);
    cudaEventRecord(evZ, s3);

    // --- Main: CSR build ---
    cudaMemsetAsync(deg, 0, (size_t)N * sizeof(int));
    sgc_hist<<<blksE256, 256>>>(dst, deg, rank, E);
    sgc_scanA<<<NB, 256>>>(deg, off, bsum, N);
    cudaEventRecord(evA, 0);

    cudaStreamWaitEvent(s2, evA, 0);
    sgc_scanC<<<blksN256, 256, 0, s2>>>(off, off2, bsum, N, NB);
    cudaEventRecord(evC, s2);

    sgc_reorder<<<reoBlks, 256>>>(src, dst, wt, off, rank, bsum, NB, csr, E,
                                  reoBlks * 256);

    // --- Join (gemm+scanC via evC, zeros via evZ), then 3 hops ---
    cudaStreamWaitEvent(0, evC, 0);
    cudaStreamWaitEvent(0, evZ, 0);
    sgc_gather_kernel<false><<<gatherBlks, 128>>>(h0, h1, nullptr, csr, E);
    sgc_gather_kernel<false><<<gatherBlks, 128>>>(h1, h2, nullptr, csr, E);
    sgc_gather_kernel<true><<<gatherBlks, 128>>>(h2, nullptr, out, csr, E);
}

// round 17
// speedup vs baseline: 1.7307x; 1.7307x over previous
#include <cuda_runtime.h>
#include <cuda_fp16.h>
#include <mma.h>
#include <stdint.h>

#define IN_F   256
#define OUT_F  64
#define MAX_NODES 100000
#define MAX_EDGES 1600000

// ---------------------------------------------------------------------------
// Device-global scratch (allocation-free)
// ---------------------------------------------------------------------------
__device__ __half g_h0[(size_t)MAX_NODES * OUT_F];   // fp16 feature ping
__device__ __half g_h1[(size_t)MAX_NODES * OUT_F];   // fp16 feature pong
__device__ int   g_deg[MAX_NODES];
__device__ int   g_off[MAX_NODES];    // partial (per-1024-block) offsets
__device__ int   g_off2[MAX_NODES];   // finalized offsets (scanC output)
__device__ int   g_rank[MAX_EDGES];
__device__ int   g_bsum[128];
__device__ __align__(16) int2 g_csr[MAX_EDGES];  // (src, wbits), dst-grouped

// ---------------------------------------------------------------------------
// Tensor-core GEMM: y[n,f] = fp16( x@W.T + b )
// ---------------------------------------------------------------------------
#define GM 128
#define ALD 24

union GemmSmem {
    struct {
        __half Ws[OUT_F * IN_F];   // 32768 B
        __half As[GM * ALD];       //  6144 B
    } in;
    float stage[GM * OUT_F];       // 32768 B
};

__global__ __launch_bounds__(256) void sgc_gemm_kernel(
    const float* __restrict__ x, const float* __restrict__ W,
    const float* __restrict__ bias, __half* __restrict__ y, int n_nodes)
{
    using namespace nvcuda;
    __shared__ GemmSmem sm;

    const int t    = threadIdx.x;
    const int warp = t >> 5;
    const int node_base = blockIdx.x * GM;

    {   // Stage W (fp32) -> fp16 smem
        const float4* src = reinterpret_cast<const float4*>(W);
        __half2* dst = reinterpret_cast<__half2*>(sm.in.Ws);
        #pragma unroll
        for (int r = 0; r < 16; r++) {
            int idx4 = t + r * 256;
            float4 v = src[idx4];
            dst[idx4 * 2 + 0] = __floats2half2_rn(v.x, v.y);
            dst[idx4 * 2 + 1] = __floats2half2_rn(v.z, v.w);
        }
    }

    wmma::fragment<wmma::accumulator, 16, 16, 16, float> c[4];
    #pragma unroll
    for (int j = 0; j < 4; j++) wmma::fill_fragment(c[j], 0.0f);

    for (int k0 = 0; k0 < IN_F; k0 += 16) {
        __syncthreads();
        #pragma unroll
        for (int r = 0; r < 2; r++) {
            int idx = t + r * 256;
            int row = idx >> 2;
            int q   = idx & 3;
            int gn  = node_base + row;
            float4 v = make_float4(0.f, 0.f, 0.f, 0.f);
            if (gn < n_nodes)
                v = *reinterpret_cast<const float4*>(x + (size_t)gn * IN_F + k0 + q * 4);
            __half2* p = reinterpret_cast<__half2*>(&sm.in.As[row * ALD + q * 4]);
            p[0] = __floats2half2_rn(v.x, v.y);
            p[1] = __floats2half2_rn(v.z, v.w);
        }
        __syncthreads();

        wmma::fragment<wmma::matrix_a, 16, 16, 16, __half, wmma::row_major> a;
        wmma::load_matrix_sync(a, &sm.in.As[warp * 16 * ALD], ALD);
        #pragma unroll
        for (int j = 0; j < 4; j++) {
            wmma::fragment<wmma::matrix_b, 16, 16, 16, __half, wmma::col_major> bf;
            wmma::load_matrix_sync(bf, &sm.in.Ws[(j * 16) * IN_F + k0], IN_F);
            wmma::mma_sync(c[j], a, bf, c[j]);
        }
    }

    __syncthreads();
    #pragma unroll
    for (int j = 0; j < 4; j++)
        wmma::store_matrix_sync(&sm.stage[(warp * 16) * OUT_F + j * 16], c[j],
                                OUT_F, wmma::mem_row_major);
    __syncthreads();

    {
        int row  = t >> 1;
        int part = (t & 1) * 32;
        int gn   = node_base + row;
        if (gn < n_nodes) {
            uint4 o[1];
            __half* oh = reinterpret_cast<__half*>(o);
            #pragma unroll
            for (int seg = 0; seg < 4; seg++) {
                #pragma unroll
                for (int cix = 0; cix < 8; cix++) {
                    int f = part + seg * 8 + cix;
                    oh[cix] = __float2half(sm.stage[row * OUT_F + f] + bias[f]);
                }
                reinterpret_cast<uint4*>(y + (size_t)gn * OUT_F + part)[seg] = o[0];
            }
        }
    }
}

// ---------------------------------------------------------------------------
// CSR build
// ---------------------------------------------------------------------------
__global__ void sgc_hist(const int* __restrict__ dst, int* __restrict__ deg,
                         int* __restrict__ rank, int E)
{
    int i = blockIdx.x * blockDim.x + threadIdx.x;
    if (i < E) rank[i] = atomicAdd(&deg[dst[i]], 1);
}

__global__ void sgc_scanA(const int* __restrict__ deg, int* __restrict__ off,
                          int* __restrict__ bsum, int n)
{
    __shared__ int s[256];
    int t = threadIdx.x;
    int base = blockIdx.x * 1024 + t * 4;
    int v0 = (base + 0 < n) ? deg[base + 0] : 0;
    int v1 = (base + 1 < n) ? deg[base + 1] : 0;
    int v2 = (base + 2 < n) ? deg[base + 2] : 0;
    int v3 = (base + 3 < n) ? deg[base + 3] : 0;
    int tsum = v0 + v1 + v2 + v3;
    s[t] = tsum;
    __syncthreads();
    for (int o = 1; o < 256; o <<= 1) {
        int xv = (t >= o) ? s[t - o] : 0;
        __syncthreads();
        s[t] += xv;
        __syncthreads();
    }
    int excl = s[t] - tsum;
    if (t == 255) bsum[blockIdx.x] = s[255];
    if (base + 0 < n) off[base + 0] = excl;
    if (base + 1 < n) off[base + 1] = excl + v0;
    if (base + 2 < n) off[base + 2] = excl + v0 + v1;
    if (base + 3 < n) off[base + 3] = excl + v0 + v1 + v2;
}

// Finalize offsets into SEPARATE off2 (race-free with concurrent reorder).
__global__ void sgc_scanC(const int* __restrict__ off, int* __restrict__ off2,
                          const int* __restrict__ bsum, int n, int nb)
{
    __shared__ int s[128];
    int t = threadIdx.x;
    if (t < 128) s[t] = (t < nb) ? bsum[t] : 0;
    __syncthreads();
    #pragma unroll
    for (int o = 1; o < 128; o <<= 1) {
        int v = (t < 128 && t >= o) ? s[t - o] : 0;
        __syncthreads();
        if (t < 128) s[t] += v;
        __syncthreads();
    }
    int i = blockIdx.x * 256 + t;
    if (i < n) {
        int blk = i >> 10;
        int pref = (blk == 0) ? 0 : s[blk - 1];
        off2[i] = off[i] + pref;
    }
}

// Reorder using PARTIAL off + in-block bsum prefix (reads only immutable data).
__global__ void sgc_reorder(const int* __restrict__ src, const int* __restrict__ dst,
                            const float* __restrict__ wt,
                            const int* __restrict__ offp, const int* __restrict__ rank,
                            const int* __restrict__ bsum, int nb,
                            int2* __restrict__ csr, int E, int T)
{
    __shared__ int s[128];
    int t = threadIdx.x;
    if (t < 128) s[t] = (t < nb) ? bsum[t] : 0;
    __syncthreads();
    #pragma unroll
    for (int o = 1; o < 128; o <<= 1) {
        int v = (t < 128 && t >= o) ? s[t - o] : 0;
        __syncthreads();
        if (t < 128) s[t] += v;
        __syncthreads();
    }

    int i0 = blockIdx.x * blockDim.x + t;
    int i1 = i0 + T, i2 = i0 + 2 * T, i3 = i0 + 3 * T;

    int d0 = (i0 < E) ? dst[i0] : 0;
    int d1 = (i1 < E) ? dst[i1] : 0;
    int d2 = (i2 < E) ? dst[i2] : 0;
    int d3 = (i3 < E) ? dst[i3] : 0;
    int r0 = (i0 < E) ? rank[i0] : 0;
    int r1 = (i1 < E) ? rank[i1] : 0;
    int r2 = (i2 < E) ? rank[i2] : 0;
    int r3 = (i3 < E) ? rank[i3] : 0;
    int o0 = __ldg(offp + d0);
    int o1 = __ldg(offp + d1);
    int o2 = __ldg(offp + d2);
    int o3 = __ldg(offp + d3);
    o0 += (d0 >> 10) ? s[(d0 >> 10) - 1] : 0;
    o1 += (d1 >> 10) ? s[(d1 >> 10) - 1] : 0;
    o2 += (d2 >> 10) ? s[(d2 >> 10) - 1] : 0;
    o3 += (d3 >> 10) ? s[(d3 >> 10) - 1] : 0;
    if (i0 < E) csr[o0 + r0] = make_int2(src[i0], __float_as_int(wt[i0]));
    if (i1 < E) csr[o1 + r1] = make_int2(src[i1], __float_as_int(wt[i1]));
    if (i2 < E) csr[o2 + r2] = make_int2(src[i2], __float_as_int(wt[i2]));
    if (i3 < E) csr[o3 + r3] = make_int2(src[i3], __float_as_int(wt[i3]));
}

// ---------------------------------------------------------------------------
// Gather hop (R14-proven): 16 lanes/node (2 nodes/warp), uint2 = 4 fp16 feats
// per lane (128B/node line). Software-pipelined: next group's csr entries
// prefetched (as 2x int4 = 4 edges) before current group's feature loads.
// ---------------------------------------------------------------------------
__device__ __forceinline__ void accE(float2& ax, float2& ay, uint2 r, float w)
{
    float2 f0 = __half22float2(*reinterpret_cast<__half2*>(&r.x));
    float2 f1 = __half22float2(*reinterpret_cast<__half2*>(&r.y));
    ax.x += w * f0.x; ax.y += w * f0.y;
    ay.x += w * f1.x; ay.y += w * f1.y;
}

template <bool LAST>
__global__ __launch_bounds__(256) void sgc_gather_kernel(
    const uint2* __restrict__ A, __half* __restrict__ Bh, float* __restrict__ Bf,
    const int* __restrict__ off, const int* __restrict__ deg,
    const int2* __restrict__ csr, int n_nodes)
{
    int warp = threadIdx.x >> 5;
    int lane = threadIdx.x & 31;
    int slot = lane >> 4;
    int fl   = lane & 15;
    int node = blockIdx.x * 16 + warp * 2 + slot;
    if (node >= n_nodes) return;

    int e   = __ldg(off + node);
    int end = e + __ldg(deg + node);

    float2 ax0 = {0.f,0.f}, ay0 = {0.f,0.f};
    float2 ax1 = {0.f,0.f}, ay1 = {0.f,0.f};

    int2 c0, c1, c2, c3;
    bool have = (e + 4 <= end);
    if (have) {
        // csr 16B-aligned only at even indices; load scalar pair-safe:
        c0 = __ldg(&csr[e]);
        c1 = __ldg(&csr[e + 1]);
        c2 = __ldg(&csr[e + 2]);
        c3 = __ldg(&csr[e + 3]);
    }

    for (; e + 8 <= end; e += 4) {
        int2 n0 = __ldg(&csr[e + 4]);
        int2 n1 = __ldg(&csr[e + 5]);
        int2 n2 = __ldg(&csr[e + 6]);
        int2 n3 = __ldg(&csr[e + 7]);
        uint2 r0 = __ldg(&A[c0.x * 16 + fl]);
        uint2 r1 = __ldg(&A[c1.x * 16 + fl]);
        uint2 r2 = __ldg(&A[c2.x * 16 + fl]);
        uint2 r3 = __ldg(&A[c3.x * 16 + fl]);
        accE(ax0, ay0, r0, __int_as_float(c0.y));
        accE(ax1, ay1, r1, __int_as_float(c1.y));
        accE(ax0, ay0, r2, __int_as_float(c2.y));
        accE(ax1, ay1, r3, __int_as_float(c3.y));
        c0 = n0; c1 = n1; c2 = n2; c3 = n3;
    }
    if (have) {
        uint2 r0 = __ldg(&A[c0.x * 16 + fl]);
        uint2 r1 = __ldg(&A[c1.x * 16 + fl]);
        uint2 r2 = __ldg(&A[c2.x * 16 + fl]);
        uint2 r3 = __ldg(&A[c3.x * 16 + fl]);
        accE(ax0, ay0, r0, __int_as_float(c0.y));
        accE(ax1, ay1, r1, __int_as_float(c1.y));
        accE(ax0, ay0, r2, __int_as_float(c2.y));
        accE(ax1, ay1, r3, __int_as_float(c3.y));
        e += 4;
    }
    for (; e < end; e++) {
        int2 ew = __ldg(&csr[e]);
        uint2 r = __ldg(&A[ew.x * 16 + fl]);
        accE(ax0, ay0, r, __int_as_float(ew.y));
    }
    ax0.x += ax1.x; ax0.y += ax1.y;
    ay0.x += ay1.x; ay0.y += ay1.y;

    if (LAST) {
        reinterpret_cast<float4*>(Bf)[(size_t)node * 16 + fl] =
            make_float4(ax0.x, ax0.y, ay0.x, ay0.y);
    } else {
        __half2 h0 = __floats2half2_rn(ax0.x, ax0.y);
        __half2 h1 = __floats2half2_rn(ay0.x, ay0.y);
        uint2 o;
        o.x = *reinterpret_cast<unsigned*>(&h0);
        o.y = *reinterpret_cast<unsigned*>(&h1);
        reinterpret_cast<uint2*>(Bh)[(size_t)node * 16 + fl] = o;
    }
}

// ---------------------------------------------------------------------------
// Launch: GEMM + scanC on side stream; CSR build + hops on main. Race-free.
// ---------------------------------------------------------------------------
extern "C" void kernel_launch(void* const* d_in, const int* in_sizes, int n_in,
                              void* d_out, int out_size)
{
    const float* x   = (const float*)d_in[0];
    const float* W   = (const float*)d_in[1];
    const float* b   = (const float*)d_in[2];
    const int*   src = (const int*)  d_in[3];
    const int*   dst = (const int*)  d_in[4];
    const float* wt  = (const float*)d_in[5];

    const int N = in_sizes[0] / IN_F;
    const int E = in_sizes[3];
    float* out  = (float*)d_out;

    __half *h0, *h1;
    int *deg, *off, *off2, *rank, *bsum;
    int2 *csr;
    cudaGetSymbolAddress((void**)&h0,   g_h0);
    cudaGetSymbolAddress((void**)&h1,   g_h1);
    cudaGetSymbolAddress((void**)&deg,  g_deg);
    cudaGetSymbolAddress((void**)&off,  g_off);
    cudaGetSymbolAddress((void**)&off2, g_off2);
    cudaGetSymbolAddress((void**)&rank, g_rank);
    cudaGetSymbolAddress((void**)&bsum, g_bsum);
    cudaGetSymbolAddress((void**)&csr,  g_csr);

    static cudaStream_t s2 = nullptr;
    static cudaEvent_t evFork = nullptr, evA = nullptr, evC = nullptr;
    if (s2 == nullptr) {
        cudaStreamCreateWithFlags(&s2, cudaStreamNonBlocking);
        cudaEventCreateWithFlags(&evFork, cudaEventDisableTiming);
        cudaEventCreateWithFlags(&evA,    cudaEventDisableTiming);
        cudaEventCreateWithFlags(&evC,    cudaEventDisableTiming);
    }

    const int NB         = (N + 1023) / 1024;
    const int blksN256   = (N + 255) / 256;
    const int blksE256   = (E + 255) / 256;
    const int gemmBlks   = (N + GM - 1) / GM;
    const int gatherBlks = (N + 15) / 16;
    const int reoT       = (E + 3) / 4;
    const int reoBlks    = (reoT + 255) / 256;

    // --- Fork side stream: GEMM (independent of CSR build) ---
    cudaEventRecord(evFork, 0);
    cudaStreamWaitEvent(s2, evFork, 0);
    sgc_gemm_kernel<<<gemmBlks, 256, 0, s2>>>(x, W, b, h0, N);

    // --- Main: CSR build ---
    cudaMemsetAsync(deg, 0, (size_t)N * sizeof(int));
    sgc_hist<<<blksE256, 256>>>(dst, deg, rank, E);
    sgc_scanA<<<NB, 256>>>(deg, off, bsum, N);
    cudaEventRecord(evA, 0);

    // scanC on side stream (writes off2; runs parallel with reorder on main)
    cudaStreamWaitEvent(s2, evA, 0);
    sgc_scanC<<<blksN256, 256, 0, s2>>>(off, off2, bsum, N, NB);
    cudaEventRecord(evC, s2);

    // reorder on main (reads partial off + bsum only; off never mutated)
    sgc_reorder<<<reoBlks, 256>>>(src, dst, wt, off, rank, bsum, NB, csr, E,
                                  reoBlks * 256);

    // --- Join (gemm + scanC), then 3 full-width gather hops on main ---
    cudaStreamWaitEvent(0, evC, 0);
    sgc_gather_kernel<false><<<gatherBlks, 256>>>((const uint2*)h0, h1, nullptr,
                                                  off2, deg, csr, N);
    sgc_gather_kernel<false><<<gatherBlks, 256>>>((const uint2*)h1, h0, nullptr,
                                                  off2, deg, csr, N);
    sgc_gather_kernel<true><<<gatherBlks, 256>>>((const uint2*)h0, nullptr, out,
                                                 off2, deg, csr, N);
}